// round 3
// baseline (speedup 1.0000x reference)
#include <cuda_runtime.h>
#include <cstdint>

// ---------------------------------------------------------------------------
// SelfAttention: out = softmax((x@Wq^T)(x@Wk^T)^T / sqrt(D)) @ (x@Wv^T)
// B=4, S=4096, D=1024.  TF32 tensor-core GEMMs + row softmax.
// ---------------------------------------------------------------------------

#define BM 128
#define BN 128
#define BK 32
#define PAD 36  // smem row stride in 32-bit words (conflict-free fragment LDS)

static const int BATCH = 4;
static const int SEQ   = 4096;
static const int DIM   = 1024;

// Scratch (device globals: allocation-free rule)
__device__ float g_Q [4LL * 4096 * 1024];
__device__ float g_K [4LL * 4096 * 1024];
__device__ float g_Vt[4LL * 1024 * 4096];   // per batch: [D][S]
__device__ float g_S [4LL * 4096 * 4096];   // scores/probs

__device__ __forceinline__ uint32_t f2tf32(float f) {
    uint32_t r;
    asm("cvt.rna.tf32.f32 %0, %1;" : "=r"(r) : "f"(f));
    return r;
}

__device__ __forceinline__ void mma_tf32(float c[4],
                                         uint32_t a0, uint32_t a1, uint32_t a2, uint32_t a3,
                                         uint32_t b0, uint32_t b1) {
    asm volatile(
        "mma.sync.aligned.m16n8k8.row.col.f32.tf32.tf32.f32 "
        "{%0,%1,%2,%3}, {%4,%5,%6,%7}, {%8,%9}, {%0,%1,%2,%3};\n"
        : "+f"(c[0]), "+f"(c[1]), "+f"(c[2]), "+f"(c[3])
        : "r"(a0), "r"(a1), "r"(a2), "r"(a3), "r"(b0), "r"(b1));
}

// C[M,N] = alpha * A[M,K] @ B[N,K]^T   (both row-major; B stored N-major)
// If TRANS_OUT: C[n*ldc + m] instead of C[m*ldc + n].
// Batched via blockIdx.z with element strides sA/sB/sC.
template <bool TRANS_OUT>
__global__ __launch_bounds__(256, 1)
void gemm_tf32(const float* __restrict__ A, const float* __restrict__ B,
               float* __restrict__ C,
               int M, int N, int K, int lda, int ldb, int ldc,
               long long sA, long long sB, long long sC, float alpha)
{
    extern __shared__ uint32_t smem[];
    uint32_t* AsBase = smem;                   // [2][BM][PAD]
    uint32_t* BsBase = smem + 2 * BM * PAD;    // [2][BN][PAD]

    A += (long long)blockIdx.z * sA;
    B += (long long)blockIdx.z * sB;
    C += (long long)blockIdx.z * sC;

    const int m0 = blockIdx.y * BM;
    const int n0 = blockIdx.x * BN;

    const int tid  = threadIdx.x;
    const int lane = tid & 31;
    const int wid  = tid >> 5;
    const int wm   = wid & 1;   // warp row (0..1), 64 rows each
    const int wn   = wid >> 1;  // warp col (0..3), 32 cols each
    const int g    = lane >> 2; // 0..7
    const int tg   = lane & 3;  // 0..3

    // global->reg staging (float4): 256 threads cover 32 rows x 32 cols / pass
    const int lrow = tid >> 3;        // 0..31
    const int lc4  = (tid & 7) * 4;   // col in floats

    float4 ra[4], rb[4];

    auto ldg_tile = [&](int k0) {
        #pragma unroll
        for (int i = 0; i < 4; i++) {
            int r = lrow + 32 * i;
            ra[i] = *reinterpret_cast<const float4*>(&A[(long long)(m0 + r) * lda + k0 + lc4]);
            rb[i] = *reinterpret_cast<const float4*>(&B[(long long)(n0 + r) * ldb + k0 + lc4]);
        }
    };
    auto sts_tile = [&](int st) {
        uint32_t* as = AsBase + st * BM * PAD;
        uint32_t* bs = BsBase + st * BN * PAD;
        #pragma unroll
        for (int i = 0; i < 4; i++) {
            int r = lrow + 32 * i;
            as[r * PAD + lc4 + 0] = f2tf32(ra[i].x);
            as[r * PAD + lc4 + 1] = f2tf32(ra[i].y);
            as[r * PAD + lc4 + 2] = f2tf32(ra[i].z);
            as[r * PAD + lc4 + 3] = f2tf32(ra[i].w);
            bs[r * PAD + lc4 + 0] = f2tf32(rb[i].x);
            bs[r * PAD + lc4 + 1] = f2tf32(rb[i].y);
            bs[r * PAD + lc4 + 2] = f2tf32(rb[i].z);
            bs[r * PAD + lc4 + 3] = f2tf32(rb[i].w);
        }
    };

    float acc[4][4][4];
    #pragma unroll
    for (int mi = 0; mi < 4; mi++)
        #pragma unroll
        for (int ni = 0; ni < 4; ni++)
            #pragma unroll
            for (int j = 0; j < 4; j++) acc[mi][ni][j] = 0.0f;

    ldg_tile(0);
    sts_tile(0);
    __syncthreads();

    const int ntiles = K / BK;
    for (int kt = 0; kt < ntiles; kt++) {
        const int st = kt & 1;
        if (kt + 1 < ntiles) ldg_tile((kt + 1) * BK);

        const uint32_t* as = AsBase + st * BM * PAD;
        const uint32_t* bs = BsBase + st * BN * PAD;

        #pragma unroll
        for (int kk = 0; kk < 4; kk++) {
            const int kb = kk * 8;
            uint32_t af[4][4], bf[4][2];
            #pragma unroll
            for (int mi = 0; mi < 4; mi++) {
                int row = wm * 64 + mi * 16 + g;
                af[mi][0] = as[row * PAD + kb + tg];
                af[mi][1] = as[(row + 8) * PAD + kb + tg];
                af[mi][2] = as[row * PAD + kb + tg + 4];
                af[mi][3] = as[(row + 8) * PAD + kb + tg + 4];
            }
            #pragma unroll
            for (int ni = 0; ni < 4; ni++) {
                int col = wn * 32 + ni * 8 + g;
                bf[ni][0] = bs[col * PAD + kb + tg];
                bf[ni][1] = bs[col * PAD + kb + tg + 4];
            }
            #pragma unroll
            for (int mi = 0; mi < 4; mi++)
                #pragma unroll
                for (int ni = 0; ni < 4; ni++)
                    mma_tf32(acc[mi][ni], af[mi][0], af[mi][1], af[mi][2], af[mi][3],
                             bf[ni][0], bf[ni][1]);
        }

        if (kt + 1 < ntiles) sts_tile((kt + 1) & 1);
        __syncthreads();
    }

    // epilogue: c0:(g,2t) c1:(g,2t+1) c2:(g+8,2t) c3:(g+8,2t+1)
    #pragma unroll
    for (int mi = 0; mi < 4; mi++) {
        #pragma unroll
        for (int ni = 0; ni < 4; ni++) {
            int row = m0 + wm * 64 + mi * 16 + g;
            int col = n0 + wn * 32 + ni * 8 + 2 * tg;
            float v0 = acc[mi][ni][0] * alpha;
            float v1 = acc[mi][ni][1] * alpha;
            float v2 = acc[mi][ni][2] * alpha;
            float v3 = acc[mi][ni][3] * alpha;
            if (!TRANS_OUT) {
                float2 p0 = make_float2(v0, v1);
                float2 p1 = make_float2(v2, v3);
                *reinterpret_cast<float2*>(&C[(long long)row * ldc + col]) = p0;
                *reinterpret_cast<float2*>(&C[(long long)(row + 8) * ldc + col]) = p1;
            } else {
                C[(long long)col * ldc + row]           = v0;
                C[(long long)(col + 1) * ldc + row]     = v1;
                C[(long long)col * ldc + row + 8]       = v2;
                C[(long long)(col + 1) * ldc + row + 8] = v3;
            }
        }
    }
}

// In-place softmax over rows of length 4096. grid = nrows, block = 256.
__global__ __launch_bounds__(256)
void softmax_rows(float* __restrict__ S)
{
    const long long row = blockIdx.x;
    float4* p = reinterpret_cast<float4*>(S + row * 4096);
    const int tid = threadIdx.x;
    __shared__ float red[8];

    float4 v[4];
    float mx = -1e30f;
    #pragma unroll
    for (int i = 0; i < 4; i++) {
        v[i] = p[tid + 256 * i];
        mx = fmaxf(mx, fmaxf(fmaxf(v[i].x, v[i].y), fmaxf(v[i].z, v[i].w)));
    }
    #pragma unroll
    for (int o = 16; o > 0; o >>= 1) mx = fmaxf(mx, __shfl_xor_sync(0xffffffffu, mx, o));
    if ((tid & 31) == 0) red[tid >> 5] = mx;
    __syncthreads();
    if (tid < 32) {
        float m = (tid < 8) ? red[tid] : -1e30f;
        #pragma unroll
        for (int o = 4; o > 0; o >>= 1) m = fmaxf(m, __shfl_xor_sync(0xffffffffu, m, o));
        if (tid == 0) red[0] = m;
    }
    __syncthreads();
    mx = red[0];
    __syncthreads();

    float sum = 0.0f;
    #pragma unroll
    for (int i = 0; i < 4; i++) {
        v[i].x = __expf(v[i].x - mx);
        v[i].y = __expf(v[i].y - mx);
        v[i].z = __expf(v[i].z - mx);
        v[i].w = __expf(v[i].w - mx);
        sum += v[i].x + v[i].y + v[i].z + v[i].w;
    }
    #pragma unroll
    for (int o = 16; o > 0; o >>= 1) sum += __shfl_xor_sync(0xffffffffu, sum, o);
    if ((tid & 31) == 0) red[tid >> 5] = sum;
    __syncthreads();
    if (tid < 32) {
        float s = (tid < 8) ? red[tid] : 0.0f;
        #pragma unroll
        for (int o = 4; o > 0; o >>= 1) s += __shfl_xor_sync(0xffffffffu, s, o);
        if (tid == 0) red[0] = s;
    }
    __syncthreads();
    const float inv = 1.0f / red[0];

    #pragma unroll
    for (int i = 0; i < 4; i++) {
        v[i].x *= inv; v[i].y *= inv; v[i].z *= inv; v[i].w *= inv;
        p[tid + 256 * i] = v[i];
    }
}

extern "C" void kernel_launch(void* const* d_in, const int* in_sizes, int n_in,
                              void* d_out, int out_size)
{
    const float* x  = (const float*)d_in[0];
    const float* Wq = (const float*)d_in[1];
    const float* Wk = (const float*)d_in[2];
    const float* Wv = (const float*)d_in[3];
    float* out = (float*)d_out;

    float *Q, *Kp, *Vt, *S;
    cudaGetSymbolAddress((void**)&Q,  g_Q);
    cudaGetSymbolAddress((void**)&Kp, g_K);
    cudaGetSymbolAddress((void**)&Vt, g_Vt);
    cudaGetSymbolAddress((void**)&S,  g_S);

    const size_t shmem = (size_t)2 * BM * PAD * 4 + (size_t)2 * BN * PAD * 4; // 73728
    cudaFuncSetAttribute(gemm_tf32<false>, cudaFuncAttributeMaxDynamicSharedMemorySize, (int)shmem);
    cudaFuncSetAttribute(gemm_tf32<true>,  cudaFuncAttributeMaxDynamicSharedMemorySize, (int)shmem);

    dim3 blk(256);
    const long long BS  = (long long)SEQ * DIM;      // 4096*1024 per batch
    const long long BSS = (long long)SEQ * SEQ;      // 4096*4096 per batch

    // Q = x @ Wq^T  (M=16384 spans all batches), K likewise
    gemm_tf32<false><<<dim3(DIM / BN, (BATCH * SEQ) / BM, 1), blk, shmem>>>(
        x, Wq, Q, BATCH * SEQ, DIM, DIM, DIM, DIM, DIM, 0, 0, 0, 1.0f);
    gemm_tf32<false><<<dim3(DIM / BN, (BATCH * SEQ) / BM, 1), blk, shmem>>>(
        x, Wk, Kp, BATCH * SEQ, DIM, DIM, DIM, DIM, DIM, 0, 0, 0, 1.0f);

    // Vt[b][d][s] = (x_b @ Wv^T)[s][d]  (transposed write, batched)
    gemm_tf32<true><<<dim3(DIM / BN, SEQ / BM, BATCH), blk, shmem>>>(
        x, Wv, Vt, SEQ, DIM, DIM, DIM, DIM, SEQ, BS, 0, BS, 1.0f);

    // S[b] = (Q_b @ K_b^T) * 1/sqrt(D)
    gemm_tf32<false><<<dim3(SEQ / BN, SEQ / BM, BATCH), blk, shmem>>>(
        Q, Kp, S, SEQ, SEQ, DIM, DIM, DIM, SEQ, BS, BS, BSS, 0.03125f);

    // row softmax over keys
    softmax_rows<<<BATCH * SEQ, 256>>>(S);

    // out[b] = P_b @ V_b   (B = Vt_b is [D][S], N-major)
    gemm_tf32<false><<<dim3(DIM / BN, SEQ / BM, BATCH), blk, shmem>>>(
        S, Vt, out, SEQ, DIM, SEQ, SEQ, SEQ, DIM, BSS, BS, BS, 1.0f);
}

// round 9
// speedup vs baseline: 2.1530x; 2.1530x over previous
#include <cuda_runtime.h>
#include <cuda_fp16.h>
#include <cstdint>

// ---------------------------------------------------------------------------
// SelfAttention: out = softmax((x@Wq^T)(x@Wk^T)^T / sqrt(D)) @ (x@Wv^T)
// B=4, S=4096, D=1024.  fp16 tensor-core GEMMs (m16n8k16, fp32 accum),
// EXACT R3 skeleton (proven to run): LDG->reg->STS staging, double buffer,
// scalar LDS fragment loads, PAD=36-word rows.  No cp.async, no ldmatrix.
// fp16 mantissa == tf32 mantissa -> same numerics as the passing R3 kernel.
// ---------------------------------------------------------------------------

#define BM 128
#define BN 128
#define BKH 64   // k-elements (halves) per tile = 32 words
#define PAD 36   // smem row stride in 32-bit words (16B-aligned, conflict-free)

static const int BATCH = 4;
static const int SEQ   = 4096;
static const int DIM   = 1024;

// Scratch (device globals: allocation-free rule)
__device__ __half g_Xh[4LL * 4096 * 1024];   // fp16 x
__device__ __half g_Wh[3LL * 1024 * 1024];   // fp16 Wq|Wk|Wv
__device__ __half g_Q [4LL * 4096 * 1024];
__device__ __half g_K [4LL * 4096 * 1024];
__device__ __half g_Vt[4LL * 1024 * 4096];   // per batch: [D][S]
__device__ float  g_S [4LL * 4096 * 4096];   // fp32 scores
__device__ __half g_P [4LL * 4096 * 4096];   // fp16 probabilities

__device__ __forceinline__ void mma_f16(float c[4],
                                        uint32_t a0, uint32_t a1, uint32_t a2, uint32_t a3,
                                        uint32_t b0, uint32_t b1) {
    asm volatile(
        "mma.sync.aligned.m16n8k16.row.col.f32.f16.f16.f32 "
        "{%0,%1,%2,%3}, {%4,%5,%6,%7}, {%8,%9}, {%0,%1,%2,%3};\n"
        : "+f"(c[0]), "+f"(c[1]), "+f"(c[2]), "+f"(c[3])
        : "r"(a0), "r"(a1), "r"(a2), "r"(a3), "r"(b0), "r"(b1));
}

// C[M,N] = alpha * A[M,K] @ B[N,K]^T   (fp16 in, fp32 accum; B stored N-major)
// OUT_HALF: C is __half else float.  TRANS_OUT: C[n*ldc + m].
// K, lda, ldb, ldc in elements (halves for A/B).  Batched via blockIdx.z.
template <bool TRANS_OUT, bool OUT_HALF>
__global__ __launch_bounds__(256, 1)
void gemm_h(const __half* __restrict__ A, const __half* __restrict__ B,
            void* __restrict__ Cv,
            int M, int N, int K, int lda, int ldb, int ldc,
            long long sA, long long sB, long long sC, float alpha)
{
    extern __shared__ uint32_t smem[];
    uint32_t* AsBase = smem;                   // [2][BM][PAD] words
    uint32_t* BsBase = smem + 2 * BM * PAD;    // [2][BN][PAD] words

    A += (long long)blockIdx.z * sA;
    B += (long long)blockIdx.z * sB;

    const int m0 = blockIdx.y * BM;
    const int n0 = blockIdx.x * BN;

    const int tid  = threadIdx.x;
    const int lane = tid & 31;
    const int wid  = tid >> 5;
    const int wm   = wid & 1;   // warp row (0..1), 64 rows each
    const int wn   = wid >> 1;  // warp col (0..3), 32 cols each
    const int g    = lane >> 2; // 0..7
    const int tg   = lane & 3;  // 0..3

    // global->reg staging: 256 threads cover 32 rows x 32 words / pass
    const int lrow = tid >> 3;        // 0..31
    const int lc   = tid & 7;         // chunk (4 words = 8 halves)

    uint4 ra[4], rb[4];

    auto ldg_tile = [&](int k0) {
        #pragma unroll
        for (int i = 0; i < 4; i++) {
            int r = lrow + 32 * i;
            ra[i] = *reinterpret_cast<const uint4*>(&A[(long long)(m0 + r) * lda + k0 + lc * 8]);
            rb[i] = *reinterpret_cast<const uint4*>(&B[(long long)(n0 + r) * ldb + k0 + lc * 8]);
        }
    };
    auto sts_tile = [&](int st) {
        uint32_t* as = AsBase + st * BM * PAD;
        uint32_t* bs = BsBase + st * BN * PAD;
        #pragma unroll
        for (int i = 0; i < 4; i++) {
            int r = lrow + 32 * i;
            *reinterpret_cast<uint4*>(&as[r * PAD + lc * 4]) = ra[i];
            *reinterpret_cast<uint4*>(&bs[r * PAD + lc * 4]) = rb[i];
        }
    };

    float acc[4][4][4];
    #pragma unroll
    for (int mi = 0; mi < 4; mi++)
        #pragma unroll
        for (int ni = 0; ni < 4; ni++)
            #pragma unroll
            for (int j = 0; j < 4; j++) acc[mi][ni][j] = 0.0f;

    ldg_tile(0);
    sts_tile(0);
    __syncthreads();

    const int ntiles = K / BKH;
    for (int kt = 0; kt < ntiles; kt++) {
        const int st = kt & 1;
        if (kt + 1 < ntiles) ldg_tile((kt + 1) * BKH);

        const uint32_t* as = AsBase + st * BM * PAD;
        const uint32_t* bs = BsBase + st * BN * PAD;

        #pragma unroll
        for (int kk = 0; kk < 4; kk++) {       // four k16 steps per 64-half tile
            const int kb = kk * 8;             // word offset
            uint32_t af[4][4], bf[4][2];
            #pragma unroll
            for (int mi = 0; mi < 4; mi++) {
                int row = wm * 64 + mi * 16 + g;
                af[mi][0] = as[row * PAD + kb + tg];
                af[mi][1] = as[(row + 8) * PAD + kb + tg];
                af[mi][2] = as[row * PAD + kb + tg + 4];
                af[mi][3] = as[(row + 8) * PAD + kb + tg + 4];
            }
            #pragma unroll
            for (int ni = 0; ni < 4; ni++) {
                int col = wn * 32 + ni * 8 + g;
                bf[ni][0] = bs[col * PAD + kb + tg];
                bf[ni][1] = bs[col * PAD + kb + tg + 4];
            }
            #pragma unroll
            for (int mi = 0; mi < 4; mi++)
                #pragma unroll
                for (int ni = 0; ni < 4; ni++)
                    mma_f16(acc[mi][ni], af[mi][0], af[mi][1], af[mi][2], af[mi][3],
                            bf[ni][0], bf[ni][1]);
        }

        if (kt + 1 < ntiles) sts_tile((kt + 1) & 1);
        __syncthreads();
    }

    // epilogue: c0:(g,2tg) c1:(g,2tg+1) c2:(g+8,2tg) c3:(g+8,2tg+1)
    #pragma unroll
    for (int mi = 0; mi < 4; mi++) {
        #pragma unroll
        for (int ni = 0; ni < 4; ni++) {
            int row = m0 + wm * 64 + mi * 16 + g;
            int col = n0 + wn * 32 + ni * 8 + 2 * tg;
            float v0 = acc[mi][ni][0] * alpha;
            float v1 = acc[mi][ni][1] * alpha;
            float v2 = acc[mi][ni][2] * alpha;
            float v3 = acc[mi][ni][3] * alpha;
            if (OUT_HALF) {
                __half* Ch = (__half*)Cv + (long long)blockIdx.z * sC;
                if (!TRANS_OUT) {
                    *reinterpret_cast<__half2*>(&Ch[(long long)row * ldc + col]) =
                        __floats2half2_rn(v0, v1);
                    *reinterpret_cast<__half2*>(&Ch[(long long)(row + 8) * ldc + col]) =
                        __floats2half2_rn(v2, v3);
                } else {
                    Ch[(long long)col * ldc + row]           = __float2half_rn(v0);
                    Ch[(long long)(col + 1) * ldc + row]     = __float2half_rn(v1);
                    Ch[(long long)col * ldc + row + 8]       = __float2half_rn(v2);
                    Ch[(long long)(col + 1) * ldc + row + 8] = __float2half_rn(v3);
                }
            } else {
                float* Cf = (float*)Cv + (long long)blockIdx.z * sC;
                *reinterpret_cast<float2*>(&Cf[(long long)row * ldc + col])       = make_float2(v0, v1);
                *reinterpret_cast<float2*>(&Cf[(long long)(row + 8) * ldc + col]) = make_float2(v2, v3);
            }
        }
    }
}

// ---------------- fp32 -> fp16 conversion ----------------
__global__ __launch_bounds__(256)
void f2h_k(const float* __restrict__ in, __half* __restrict__ out, int n4)
{
    int i = blockIdx.x * blockDim.x + threadIdx.x;
    if (i < n4) {
        float4 v = reinterpret_cast<const float4*>(in)[i];
        __half2* o = reinterpret_cast<__half2*>(out);
        o[2 * i + 0] = __floats2half2_rn(v.x, v.y);
        o[2 * i + 1] = __floats2half2_rn(v.z, v.w);
    }
}

// ---------------- softmax: fp32 score row -> fp16 prob row ----------------
__global__ __launch_bounds__(256)
void softmax_rows(const float* __restrict__ S, __half* __restrict__ P)
{
    const long long row = blockIdx.x;
    const float4* p = reinterpret_cast<const float4*>(S + row * 4096);
    __half2* ph = reinterpret_cast<__half2*>(P + row * 4096);
    const int tid = threadIdx.x;
    __shared__ float red[8];

    float4 v[4];
    float mx = -1e30f;
    #pragma unroll
    for (int i = 0; i < 4; i++) {
        v[i] = p[tid + 256 * i];
        mx = fmaxf(mx, fmaxf(fmaxf(v[i].x, v[i].y), fmaxf(v[i].z, v[i].w)));
    }
    #pragma unroll
    for (int o = 16; o > 0; o >>= 1) mx = fmaxf(mx, __shfl_xor_sync(0xffffffffu, mx, o));
    if ((tid & 31) == 0) red[tid >> 5] = mx;
    __syncthreads();
    if (tid < 32) {
        float m = (tid < 8) ? red[tid] : -1e30f;
        #pragma unroll
        for (int o = 4; o > 0; o >>= 1) m = fmaxf(m, __shfl_xor_sync(0xffffffffu, m, o));
        if (tid == 0) red[0] = m;
    }
    __syncthreads();
    mx = red[0];
    __syncthreads();

    float sum = 0.0f;
    #pragma unroll
    for (int i = 0; i < 4; i++) {
        v[i].x = __expf(v[i].x - mx);
        v[i].y = __expf(v[i].y - mx);
        v[i].z = __expf(v[i].z - mx);
        v[i].w = __expf(v[i].w - mx);
        sum += v[i].x + v[i].y + v[i].z + v[i].w;
    }
    #pragma unroll
    for (int o = 16; o > 0; o >>= 1) sum += __shfl_xor_sync(0xffffffffu, sum, o);
    if ((tid & 31) == 0) red[tid >> 5] = sum;
    __syncthreads();
    if (tid < 32) {
        float s = (tid < 8) ? red[tid] : 0.0f;
        #pragma unroll
        for (int o = 4; o > 0; o >>= 1) s += __shfl_xor_sync(0xffffffffu, s, o);
        if (tid == 0) red[0] = s;
    }
    __syncthreads();
    const float inv = 1.0f / red[0];

    #pragma unroll
    for (int i = 0; i < 4; i++) {
        int idx = tid + 256 * i;
        ph[2 * idx + 0] = __floats2half2_rn(v[i].x * inv, v[i].y * inv);
        ph[2 * idx + 1] = __floats2half2_rn(v[i].z * inv, v[i].w * inv);
    }
}

// ---------------- launch ----------------
extern "C" void kernel_launch(void* const* d_in, const int* in_sizes, int n_in,
                              void* d_out, int out_size)
{
    const float* x  = (const float*)d_in[0];
    const float* Wq = (const float*)d_in[1];
    const float* Wk = (const float*)d_in[2];
    const float* Wv = (const float*)d_in[3];
    float* out = (float*)d_out;

    __half *Xh, *Wh, *Q, *Kp, *Vt, *P;
    float *S;
    cudaGetSymbolAddress((void**)&Xh, g_Xh);
    cudaGetSymbolAddress((void**)&Wh, g_Wh);
    cudaGetSymbolAddress((void**)&Q,  g_Q);
    cudaGetSymbolAddress((void**)&Kp, g_K);
    cudaGetSymbolAddress((void**)&Vt, g_Vt);
    cudaGetSymbolAddress((void**)&S,  g_S);
    cudaGetSymbolAddress((void**)&P,  g_P);

    const size_t shmem = (size_t)2 * BM * PAD * 4 + (size_t)2 * BN * PAD * 4; // 73728
    cudaFuncSetAttribute(gemm_h<false, true>,  cudaFuncAttributeMaxDynamicSharedMemorySize, (int)shmem);
    cudaFuncSetAttribute(gemm_h<true,  true>,  cudaFuncAttributeMaxDynamicSharedMemorySize, (int)shmem);
    cudaFuncSetAttribute(gemm_h<false, false>, cudaFuncAttributeMaxDynamicSharedMemorySize, (int)shmem);

    const long long BS  = (long long)SEQ * DIM;      // per-batch elems
    const long long BSS = (long long)SEQ * SEQ;
    const int WN = DIM * DIM;
    dim3 blk(256);

    // inputs -> fp16
    f2h_k<<<(BATCH * SEQ * DIM / 4 + 255) / 256, blk>>>(x,  Xh,           BATCH * SEQ * DIM / 4);
    f2h_k<<<(WN / 4 + 255) / 256, blk>>>(Wq, Wh + 0LL * WN, WN / 4);
    f2h_k<<<(WN / 4 + 255) / 256, blk>>>(Wk, Wh + 1LL * WN, WN / 4);
    f2h_k<<<(WN / 4 + 255) / 256, blk>>>(Wv, Wh + 2LL * WN, WN / 4);

    // Q = X @ Wq^T ; K = X @ Wk^T   (M spans all batches), fp16 outputs
    gemm_h<false, true><<<dim3(DIM / BN, BATCH * SEQ / BM, 1), blk, shmem>>>(
        Xh, Wh + 0LL * WN, Q, BATCH * SEQ, DIM, DIM, DIM, DIM, DIM, 0, 0, 0, 1.0f);
    gemm_h<false, true><<<dim3(DIM / BN, BATCH * SEQ / BM, 1), blk, shmem>>>(
        Xh, Wh + 1LL * WN, Kp, BATCH * SEQ, DIM, DIM, DIM, DIM, DIM, 0, 0, 0, 1.0f);

    // Vt[b][d][s] = (x_b @ Wv^T)[s][d]  (transposed fp16 write, batched)
    gemm_h<true, true><<<dim3(DIM / BN, SEQ / BM, BATCH), blk, shmem>>>(
        Xh, Wh + 2LL * WN, Vt, SEQ, DIM, DIM, DIM, DIM, SEQ, BS, 0, BS, 1.0f);

    // S[b] = (Q_b @ K_b^T) / 32   (fp32 scores)
    gemm_h<false, false><<<dim3(SEQ / BN, SEQ / BM, BATCH), blk, shmem>>>(
        Q, Kp, S, SEQ, SEQ, DIM, DIM, DIM, SEQ, BS, BS, BSS, 0.03125f);

    // P = softmax(S) rows, fp16
    softmax_rows<<<BATCH * SEQ, blk>>>(S, P);

    // out[b] = P_b @ V_b   (fp32 output)
    gemm_h<false, false><<<dim3(DIM / BN, SEQ / BM, BATCH), blk, shmem>>>(
        P, Vt, out, SEQ, DIM, SEQ, SEQ, SEQ, DIM, BSS, BS, BS, 1.0f);
}